// round 1
// baseline (speedup 1.0000x reference)
#include <cuda_runtime.h>
#include <cstdint>

#define BB    2048
#define TSEQ  512
#define HH    51
#define TTOT  544      // TSEQ + 32 future
#define EPC   16       // batch elements per CTA
#define NCTA  128      // EPC * NCTA == BB
#define NTHR  256      // 64 j-lanes x 4 groups
#define WROW  212      // floats per j-row in rearranged weights (53 16B-chunks * 4)
#define HROW  104      // floats per element row in duplicated-h arrays (52 * 2)

#define W_SZ   (51 * WROW)      // 10812 floats per weight matrix
#define XS_SZ  (EPC * TSEQ)     // 8192
#define HD_SZ  (EPC * HROW)     // 1664
#define SM_FLOATS (3*W_SZ + XS_SZ + 2*HD_SZ + 256 + 256 + 256 + 64 + 16)
#define SM_BYTES  (SM_FLOATS * 4)

// ---------------- packed f32x2 helpers ----------------
__device__ __forceinline__ unsigned long long ffma2(unsigned long long a,
                                                    unsigned long long b,
                                                    unsigned long long c) {
    unsigned long long d;
    asm("fma.rn.f32x2 %0, %1, %2, %3;" : "=l"(d) : "l"(a), "l"(b), "l"(c));
    return d;
}
__device__ __forceinline__ unsigned long long pack2(float lo, float hi) {
    unsigned long long d;
    asm("mov.b64 %0, {%1, %2};" : "=l"(d) : "f"(lo), "f"(hi));
    return d;
}
__device__ __forceinline__ float2 unpack2(unsigned long long v) {
    float2 r;
    asm("mov.b64 {%0, %1}, %2;" : "=f"(r.x), "=f"(r.y) : "l"(v));
    return r;
}
// fast, accurate-enough (rel err ~1e-6) activations
__device__ __forceinline__ float sigf(float x) {
    return __fdividef(1.0f, 1.0f + __expf(-x));
}
__device__ __forceinline__ float tanhf_fast(float x) {
    return __fdividef(2.0f, 1.0f + __expf(-2.0f * x)) - 1.0f;
}

// accumulate z(4 gates, 4 elements) += W[j,:,:] . h[e,:]  (f32x2, gate-paired)
__device__ __forceinline__ void matvec_acc(const float* __restrict__ Wrow,
                                           const float* __restrict__ hrow,
                                           unsigned long long aif[4],
                                           unsigned long long ago[4]) {
#pragma unroll 13
    for (int kb = 0; kb < 26; kb++) {
        ulonglong2 wk  = *(const ulonglong2*)(Wrow + kb * 8);      // {wi,wf},{wg,wo} @ k
        ulonglong2 wk1 = *(const ulonglong2*)(Wrow + kb * 8 + 4);  // same @ k+1
#pragma unroll
        for (int m = 0; m < 4; m++) {
            ulonglong2 hp = *(const ulonglong2*)(hrow + m * HROW + kb * 4); // {h,h},{h',h'}
            aif[m] = ffma2(wk.x,  hp.x, aif[m]);
            ago[m] = ffma2(wk.y,  hp.x, ago[m]);
            aif[m] = ffma2(wk1.x, hp.y, aif[m]);
            ago[m] = ffma2(wk1.y, hp.y, ago[m]);
        }
    }
}

__global__ void __launch_bounds__(NTHR, 1)
lstm_seq_kernel(const float* __restrict__ input,
                const float* __restrict__ Wih1, const float* __restrict__ Whh1,
                const float* __restrict__ bih1, const float* __restrict__ bhh1,
                const float* __restrict__ Wih2, const float* __restrict__ Whh2,
                const float* __restrict__ bih2, const float* __restrict__ bhh2,
                const float* __restrict__ Wlin, const float* __restrict__ blin,
                float* __restrict__ out) {
    extern __shared__ float sm[];
    float* W1    = sm;                 // [51][53 chunks][4 gates]
    float* W2i   = W1  + W_SZ;
    float* W2h   = W2i + W_SZ;
    float* xs    = W2h + W_SZ;         // [16][512]
    float* hd1   = xs  + XS_SZ;        // [16][52] float2 duplicated h1
    float* hd2   = hd1 + HD_SZ;        // [16][52] float2 duplicated h2
    float* wih1q = hd2 + HD_SZ;        // [64][4]
    float* b1q   = wih1q + 256;        // [64][4]
    float* b2q   = b1q   + 256;        // [64][4]
    float* wlin  = b2q   + 256;        // [64]
    float* outb  = wlin  + 64;         // [16]

    const int tid = threadIdx.x;
    const int g   = tid >> 6;          // group 0..3 (4 elements each)
    const int j   = tid & 63;          // hidden unit lane, active if < 51
    const int jj  = (j < HH) ? j : (HH - 1);   // clamped for safe smem reads
    const int b0  = blockIdx.x * EPC;
    const int e0  = g * 4;

    // ---------- one-time init: rearrange weights, stage inputs ----------
    for (int idx = tid; idx < 51 * 52; idx += NTHR) {
        int jr = idx / 52;
        int k  = idx - jr * 52;
        bool ok = (k < 51);
#pragma unroll
        for (int gg = 0; gg < 4; gg++) {
            int r = gg * 51 + jr;
            W1 [jr * WROW + k * 4 + gg] = ok ? Whh1[r * 51 + k] : 0.f;
            W2i[jr * WROW + k * 4 + gg] = ok ? Wih2[r * 51 + k] : 0.f;
            W2h[jr * WROW + k * 4 + gg] = ok ? Whh2[r * 51 + k] : 0.f;
        }
    }
    if (tid < 51) {
#pragma unroll
        for (int gg = 0; gg < 4; gg++) {
            wih1q[tid * 4 + gg] = Wih1[gg * 51 + tid];                       // [204,1]
            b1q  [tid * 4 + gg] = bih1[gg * 51 + tid] + bhh1[gg * 51 + tid];
            b2q  [tid * 4 + gg] = bih2[gg * 51 + tid] + bhh2[gg * 51 + tid];
        }
        wlin[tid] = Wlin[tid];
    }
    for (int idx = tid; idx < XS_SZ; idx += NTHR) {
        int e = idx >> 9, tc = idx & 511;
        xs[idx] = input[(size_t)(b0 + e) * TSEQ + tc];
    }
    for (int idx = tid; idx < HD_SZ; idx += NTHR) { hd1[idx] = 0.f; hd2[idx] = 0.f; }
    const float blin_r = blin[0];
    __syncthreads();

    float c1[4] = {0, 0, 0, 0}, c2[4] = {0, 0, 0, 0};
    const float*  W1r  = W1  + jj * WROW;
    const float*  W2ir = W2i + jj * WROW;
    const float*  W2hr = W2h + jj * WROW;
    const float4  wx   = *(const float4*)(wih1q + jj * 4);
    const float4  bq1  = *(const float4*)(b1q   + jj * 4);
    const float4  bq2  = *(const float4*)(b2q   + jj * 4);
    const float   wl   = (j < HH) ? wlin[j] : 0.f;
    const float*  hd1g = hd1 + e0 * HROW;
    const float*  hd2g = hd2 + e0 * HROW;

    // ---------- sequential scan: T teacher-forced + 32 feedback steps ----------
    for (int t = 0; t < TTOT; t++) {
        float xm[4];
        if (t < TSEQ) {
#pragma unroll
            for (int m = 0; m < 4; m++) xm[m] = xs[(e0 + m) * TSEQ + t];
        } else {
#pragma unroll
            for (int m = 0; m < 4; m++) xm[m] = outb[e0 + m];   // out[t-1]
        }

        // ---- layer 1 ----
        unsigned long long aif[4], ago[4];
#pragma unroll
        for (int m = 0; m < 4; m++) {
            aif[m] = pack2(fmaf(wx.x, xm[m], bq1.x), fmaf(wx.y, xm[m], bq1.y));
            ago[m] = pack2(fmaf(wx.z, xm[m], bq1.z), fmaf(wx.w, xm[m], bq1.w));
        }
        matvec_acc(W1r, hd1g, aif, ago);

        float h1n[4];
#pragma unroll
        for (int m = 0; m < 4; m++) {
            float2 gif = unpack2(aif[m]);
            float2 ggo = unpack2(ago[m]);
            float ig = sigf(gif.x), fg = sigf(gif.y);
            float gg = tanhf_fast(ggo.x), og = sigf(ggo.y);
            c1[m]  = fg * c1[m] + ig * gg;
            h1n[m] = og * tanhf_fast(c1[m]);
        }
        __syncthreads();                                  // S1: old hd1 / outb reads done
        if (j < HH) {
#pragma unroll
            for (int m = 0; m < 4; m++)
                *(float2*)(hd1 + (e0 + m) * HROW + 2 * j) = make_float2(h1n[m], h1n[m]);
        }
        if (tid < EPC) outb[tid] = blin_r;                // re-init this step's output
        __syncthreads();                                  // S2: new hd1 visible

        // ---- layer 2 ----
#pragma unroll
        for (int m = 0; m < 4; m++) {
            aif[m] = pack2(bq2.x, bq2.y);
            ago[m] = pack2(bq2.z, bq2.w);
        }
        matvec_acc(W2ir, hd1g, aif, ago);   // W_ih2 @ h1(new)
        matvec_acc(W2hr, hd2g, aif, ago);   // W_hh2 @ h2(old)

        float h2n[4];
#pragma unroll
        for (int m = 0; m < 4; m++) {
            float2 gif = unpack2(aif[m]);
            float2 ggo = unpack2(ago[m]);
            float ig = sigf(gif.x), fg = sigf(gif.y);
            float gg = tanhf_fast(ggo.x), og = sigf(ggo.y);
            c2[m]  = fg * c2[m] + ig * gg;
            h2n[m] = og * tanhf_fast(c2[m]);
        }
        __syncthreads();                                  // S3: old hd2 reads done
        if (j < HH) {
#pragma unroll
            for (int m = 0; m < 4; m++)
                *(float2*)(hd2 + (e0 + m) * HROW + 2 * j) = make_float2(h2n[m], h2n[m]);
        }
        // out[e] = sum_j wlin[j]*h2[j] + blin : butterfly + shared atomic
#pragma unroll
        for (int m = 0; m < 4; m++) {
            float p = (j < HH) ? wl * h2n[m] : 0.f;
#pragma unroll
            for (int off = 16; off > 0; off >>= 1)
                p += __shfl_xor_sync(0xffffffffu, p, off);
            if ((tid & 31) == 0) atomicAdd(&outb[e0 + m], p);
        }
        __syncthreads();                                  // S4: outb + hd2 complete
        if (tid < EPC)
            out[(size_t)(b0 + tid) * TTOT + t] = outb[tid];
    }
}

extern "C" void kernel_launch(void* const* d_in, const int* in_sizes, int n_in,
                              void* d_out, int out_size) {
    const float* input = (const float*)d_in[0];
    const float* Wih1  = (const float*)d_in[1];
    const float* Whh1  = (const float*)d_in[2];
    const float* bih1  = (const float*)d_in[3];
    const float* bhh1  = (const float*)d_in[4];
    const float* Wih2  = (const float*)d_in[5];
    const float* Whh2  = (const float*)d_in[6];
    const float* bih2  = (const float*)d_in[7];
    const float* bhh2  = (const float*)d_in[8];
    const float* Wlin  = (const float*)d_in[9];
    const float* blin  = (const float*)d_in[10];
    // d_in[11] = "future" (=32), baked in as a constant.

    cudaFuncSetAttribute(lstm_seq_kernel,
                         cudaFuncAttributeMaxDynamicSharedMemorySize, SM_BYTES);
    lstm_seq_kernel<<<NCTA, NTHR, SM_BYTES>>>(input, Wih1, Whh1, bih1, bhh1,
                                              Wih2, Whh2, bih2, bhh2,
                                              Wlin, blin, (float*)d_out);
}